// round 2
// baseline (speedup 1.0000x reference)
#include <cuda_runtime.h>
#include <cuda_bf16.h>

// NDFT type-2: y[b,m] = sum_{k1=-32..31} sum_{k2=-32..31}
//                f_hat[b, k1+32, k2+32] * exp(-2*pi*i*(k1*x1 + k2*x2))
// x: [B, M, 2] float32, f_hat: [B, 64, 64] float32
// out: [B, M] complex64 -> interleaved (re, im) float32 pairs, OR real part
// only, depending on out_size (selected at launch).

#define B_DIM 2
#define M_DIM 8192
#define N1 64
#define N2 64
#define K_TOT (N1 * N2)
#define TPB 128          // threads per block (one sample point per thread)
#define BLOCKS_PER_B (M_DIM / TPB)   // 64

__global__ __launch_bounds__(TPB) void ndft_kernel(
    const float* __restrict__ x,      // [B, M, 2]
    const float* __restrict__ f_hat,  // [B, 64, 64]
    float* __restrict__ out,          // see real_only
    const int real_only)
{
    __shared__ float sf[K_TOT];      // 16 KB: this batch's coefficients

    const int b = blockIdx.x / BLOCKS_PER_B;
    const int mblk = blockIdx.x % BLOCKS_PER_B;
    const int m = mblk * TPB + threadIdx.x;

    // cooperative load of f_hat[b] into shared (float4 vectorized)
    {
        const float4* src = reinterpret_cast<const float4*>(f_hat + b * K_TOT);
        float4* dst = reinterpret_cast<float4*>(sf);
        #pragma unroll
        for (int i = threadIdx.x; i < K_TOT / 4; i += TPB)
            dst[i] = src[i];
    }
    __syncthreads();

    const float x1 = x[(b * M_DIM + m) * 2 + 0];
    const float x2 = x[(b * M_DIM + m) * 2 + 1];

    // Twiddles (sincospif: arg in units of pi -> exact range reduction)
    // w1  = exp(-2*pi*i*x1)            angle/pi = -2*x1
    // e1_0 = exp(-2*pi*i*(-32)*x1)     angle/pi = +64*x1
    // w2  = exp(-2*pi*i*x2)
    // e2_0 = exp(-2*pi*i*(-32)*x2)
    float w1r, w1i, e1r, e1i, w2r, w2i, e20r, e20i;
    sincospif(-2.0f * x1, &w1i, &w1r);
    sincospif(64.0f * x1, &e1i, &e1r);
    sincospif(-2.0f * x2, &w2i, &w2r);
    sincospif(64.0f * x2, &e20i, &e20r);

    // w2^2 for the two staggered inner chains
    const float w2sr = w2r * w2r - w2i * w2i;
    const float w2si = 2.0f * w2r * w2i;

    float yr0 = 0.f, yi0 = 0.f, yr1 = 0.f, yi1 = 0.f;

    #pragma unroll 1
    for (int i1 = 0; i1 < N1; ++i1) {
        // c = e1 * e2_0  (exact anchor each row)
        float c0r = e1r * e20r - e1i * e20i;
        float c0i = e1r * e20i + e1i * e20r;
        // second chain: c1 = c0 * w2
        float c1r = c0r * w2r - c0i * w2i;
        float c1i = c0r * w2i + c0i * w2r;

        const float2* frow = reinterpret_cast<const float2*>(sf + i1 * N2);

        #pragma unroll
        for (int j = 0; j < N2 / 2; ++j) {
            const float2 f2 = frow[j];   // broadcast LDS.64 (all lanes same addr)
            yr0 = fmaf(f2.x, c0r, yr0);
            yi0 = fmaf(f2.x, c0i, yi0);
            yr1 = fmaf(f2.y, c1r, yr1);
            yi1 = fmaf(f2.y, c1i, yi1);
            // advance both chains by w2^2 (independent -> 2x ILP)
            const float t0r = c0r * w2sr - c0i * w2si;
            const float t0i = c0r * w2si + c0i * w2sr;
            const float t1r = c1r * w2sr - c1i * w2si;
            const float t1i = c1r * w2si + c1i * w2sr;
            c0r = t0r; c0i = t0i;
            c1r = t1r; c1i = t1i;
        }

        // e1 *= w1
        const float ner = e1r * w1r - e1i * w1i;
        const float nei = e1r * w1i + e1i * w1r;
        e1r = ner; e1i = nei;
    }

    const float yr = yr0 + yr1;
    const float yi = yi0 + yi1;

    if (real_only) {
        out[b * M_DIM + m] = yr;
    } else {
        reinterpret_cast<float2*>(out)[b * M_DIM + m] = make_float2(yr, yi);
    }
}

extern "C" void kernel_launch(void* const* d_in, const int* in_sizes, int n_in,
                              void* d_out, int out_size) {
    // Select inputs by ELEMENT COUNT, not position (metadata order may be
    // alphabetical: "f_hat" < "x").
    //   x     : B*M*D = 2*8192*2 = 32768 elements
    //   f_hat : B*N1*N2 = 2*64*64 = 8192 elements
    const float* x;
    const float* f_hat;
    if (in_sizes[0] == B_DIM * M_DIM * 2) {
        x = (const float*)d_in[0];
        f_hat = (const float*)d_in[1];
    } else {
        x = (const float*)d_in[1];
        f_hat = (const float*)d_in[0];
    }

    float* out = (float*)d_out;
    // out_size == B*M      -> real part only (complex64 cast to float32)
    // out_size == B*M*2    -> interleaved (re, im) pairs (complex64 viewed)
    const int real_only = (out_size == B_DIM * M_DIM) ? 1 : 0;

    ndft_kernel<<<B_DIM * BLOCKS_PER_B, TPB>>>(x, f_hat, out, real_only);
}

// round 3
// speedup vs baseline: 1.5529x; 1.5529x over previous
#include <cuda_runtime.h>
#include <cuda_bf16.h>

// NDFT type-2: y[b,m] = sum_{k1,k2=-32..31} f_hat[b,k1+32,k2+32]
//                        * exp(-2*pi*i*(k1*x1 + k2*x2))
//
// Factorization: k2 = 8a + c - 32,  a,c in [0,8)
//   e2[k2] = E2c[a] * E2f[c],  E2c[a]=exp(-2pi*i*(8a-32)*x2), E2f[c]=exp(-2pi*i*c*x2)
//   y = sum_c E2f[c] * S[c],   S[c] = sum_{k1,a} f[k1, 8a+c] * (e1[k1]*E2c[a])
//
// S[c] accumulated with packed fma.rn.f32x2 (c-pairs). k1 range split across
// two adjacent lanes; combined with shfl.xor.

#define B_DIM 2
#define M_DIM 8192
#define N1 64
#define N2 64
#define K_TOT (N1 * N2)
#define TPB 128
#define PTS_PER_BLOCK (TPB / 2)                // 64 points, 2 lanes each
#define BLOCKS_PER_B (M_DIM / PTS_PER_BLOCK)   // 128

typedef unsigned long long ull;

#define PACK2(d, lo, hi) \
    asm("mov.b64 %0, {%1, %2};" : "=l"(d) \
        : "r"(__float_as_uint(lo)), "r"(__float_as_uint(hi)))
#define FMA2(d, a, b, c) \
    asm("fma.rn.f32x2 %0, %1, %2, %3;" : "=l"(d) : "l"(a), "l"(b), "l"(c))
#define UNPACK2(lo, hi, s) do { unsigned int _l, _h; \
    asm("mov.b64 {%0, %1}, %2;" : "=r"(_l), "=r"(_h) : "l"(s)); \
    (lo) = __uint_as_float(_l); (hi) = __uint_as_float(_h); } while (0)

__global__ __launch_bounds__(TPB) void ndft_kernel(
    const float* __restrict__ x,      // [B, M, 2]
    const float* __restrict__ f_hat,  // [B, 64, 64]
    float* __restrict__ out,
    const int real_only)
{
    __shared__ __align__(16) float sf[K_TOT];   // 16 KB coefficients

    const int b    = blockIdx.x / BLOCKS_PER_B;
    const int mblk = blockIdx.x % BLOCKS_PER_B;
    const int tid  = threadIdx.x;
    const int half = tid & 1;                    // k1 half: 0 -> [-32,0), 1 -> [0,32)
    const int m    = mblk * PTS_PER_BLOCK + (tid >> 1);

    // cooperative load of f_hat[b] into shared
    {
        const float4* src = reinterpret_cast<const float4*>(f_hat + b * K_TOT);
        float4* dst = reinterpret_cast<float4*>(sf);
        #pragma unroll
        for (int i = tid; i < K_TOT / 4; i += TPB)
            dst[i] = src[i];
    }
    __syncthreads();

    const float x1 = x[(b * M_DIM + m) * 2 + 0];
    const float x2 = x[(b * M_DIM + m) * 2 + 1];

    // Twiddles via sincospif (arg in units of pi; exact range reduction).
    float w1r, w1i;                 // w1 = exp(-2*pi*i*x1)
    sincospif(-2.0f * x1, &w1i, &w1r);
    float e1r, e1i;                 // e1 = exp(-2*pi*i*k1start*x1)
    if (half == 0) {                // k1start = -32 -> angle/pi = +64*x1
        sincospif(64.0f * x1, &e1i, &e1r);
    } else {                        // k1start = 0
        e1r = 1.0f; e1i = 0.0f;
    }
    float w2r, w2i;                 // w2 = exp(-2*pi*i*x2)
    sincospif(-2.0f * x2, &w2i, &w2r);
    float W8r, W8i;                 // W8 = exp(-16*pi*i*x2) = w2^8
    sincospif(-16.0f * x2, &W8i, &W8r);
    float C0r, C0i;                 // E2c[0] = exp(+64*pi*i*x2)
    sincospif(64.0f * x2, &C0i, &C0r);

    // E2f[c] = w2^c, E2c[a] = E2c[0] * W8^a  (short recurrences, 7 steps)
    float E2fr[8], E2fi[8], E2cr[8], E2ci[8];
    E2fr[0] = 1.0f; E2fi[0] = 0.0f;
    E2cr[0] = C0r;  E2ci[0] = C0i;
    #pragma unroll
    for (int i = 1; i < 8; ++i) {
        E2fr[i] = E2fr[i-1] * w2r - E2fi[i-1] * w2i;
        E2fi[i] = E2fr[i-1] * w2i + E2fi[i-1] * w2r;
        E2cr[i] = E2cr[i-1] * W8r - E2ci[i-1] * W8i;
        E2ci[i] = E2cr[i-1] * W8i + E2ci[i-1] * W8r;
    }

    // Packed accumulators: sr2[p] = (S_re[2p], S_re[2p+1]), si2[p] = imag.
    ull sr2[4] = {0ull, 0ull, 0ull, 0ull};
    ull si2[4] = {0ull, 0ull, 0ull, 0ull};

    #pragma unroll 1
    for (int i1 = 0; i1 < 32; ++i1) {
        const int row = half * 32 + i1;
        const ulonglong2* frow =
            reinterpret_cast<const ulonglong2*>(sf + row * N2);

        #pragma unroll
        for (int a = 0; a < 8; ++a) {
            // g = e1 * E2c[a]
            const float gr = e1r * E2cr[a] - e1i * E2ci[a];
            const float gi = e1r * E2ci[a] + e1i * E2cr[a];
            ull grr, gii;
            PACK2(grr, gr, gr);
            PACK2(gii, gi, gi);

            // f[row, 8a .. 8a+7]: two LDS.128, lanes broadcast
            const ulonglong2 f01 = frow[a * 2 + 0];  // pairs (c=0,1),(c=2,3)
            const ulonglong2 f23 = frow[a * 2 + 1];  // pairs (c=4,5),(c=6,7)

            FMA2(sr2[0], f01.x, grr, sr2[0]);
            FMA2(si2[0], f01.x, gii, si2[0]);
            FMA2(sr2[1], f01.y, grr, sr2[1]);
            FMA2(si2[1], f01.y, gii, si2[1]);
            FMA2(sr2[2], f23.x, grr, sr2[2]);
            FMA2(si2[2], f23.x, gii, si2[2]);
            FMA2(sr2[3], f23.y, grr, sr2[3]);
            FMA2(si2[3], f23.y, gii, si2[3]);
        }

        // e1 *= w1
        const float t = e1r * w1r - e1i * w1i;
        e1i = e1r * w1i + e1i * w1r;
        e1r = t;
    }

    // y = sum_c E2f[c] * S[c]
    float yr = 0.0f, yi = 0.0f;
    #pragma unroll
    for (int p = 0; p < 4; ++p) {
        float s0r, s1r, s0i, s1i;
        UNPACK2(s0r, s1r, sr2[p]);
        UNPACK2(s0i, s1i, si2[p]);
        const int c0 = 2 * p, c1 = 2 * p + 1;
        yr += E2fr[c0] * s0r - E2fi[c0] * s0i;
        yi += E2fr[c0] * s0i + E2fi[c0] * s0r;
        yr += E2fr[c1] * s1r - E2fi[c1] * s1i;
        yi += E2fr[c1] * s1i + E2fi[c1] * s1r;
    }

    // combine the two k1 halves (adjacent lanes)
    yr += __shfl_xor_sync(0xffffffffu, yr, 1);
    yi += __shfl_xor_sync(0xffffffffu, yi, 1);

    if (half == 0) {
        if (real_only) {
            out[b * M_DIM + m] = yr;
        } else {
            reinterpret_cast<float2*>(out)[b * M_DIM + m] = make_float2(yr, yi);
        }
    }
}

extern "C" void kernel_launch(void* const* d_in, const int* in_sizes, int n_in,
                              void* d_out, int out_size) {
    // Select inputs by element count (metadata order may differ):
    //   x: 2*8192*2 = 32768, f_hat: 2*64*64 = 8192
    const float* x;
    const float* f_hat;
    if (in_sizes[0] == B_DIM * M_DIM * 2) {
        x = (const float*)d_in[0];
        f_hat = (const float*)d_in[1];
    } else {
        x = (const float*)d_in[1];
        f_hat = (const float*)d_in[0];
    }

    float* out = (float*)d_out;
    const int real_only = (out_size == B_DIM * M_DIM) ? 1 : 0;

    ndft_kernel<<<B_DIM * BLOCKS_PER_B, TPB>>>(x, f_hat, out, real_only);
}